// round 8
// baseline (speedup 1.0000x reference)
#include <cuda_runtime.h>
#include <math_constants.h>

// Problem constants (fixed by the dataset)
#define B_      128
#define L_I     2
#define L_Q     10
#define N_ACT   8
#define IM      64
#define IMP     66
#define NPIX    4096
#define NTHR    512
#define TILE    32         // output rows per CTA (fast path)
#define TILES   2
#define INROWS  36         // TILE + 4 halo input rows
#define ISTR    72         // input smem row stride; data cols [4..67], halos 3 & 68
#define RROWS   34         // TILE + 2 halo r rows
#define RSTR    68         // r smem row stride; data cols [1..64], halos 0 & 65

#define Q_ELEMS   (B_ * L_Q * NPIX)       // 5242880
#define LOGIT_OFF Q_ELEMS
#define ACT_OFF   (Q_ELEMS + B_ * N_ACT)  // 5243904

// ---- grid-wide argmax state (self-resetting each launch -> graph-replay safe) ----
__device__ unsigned long long g_best  = 0ULL;
__device__ unsigned int       g_count = 0u;

// slow-path (w != 0) scratch — never touched on the fast path
__device__ float g_r  [B_][IMP * IMP];
__device__ float g_qr [B_][L_Q][NPIX];
__device__ float g_vb [2][B_][IMP * IMP];

typedef unsigned long long ull;
__device__ __forceinline__ ull pk2(float x, float y) {
    ull r; asm("mov.b64 %0,{%1,%2};" : "=l"(r) : "f"(x), "f"(y)); return r;
}
__device__ __forceinline__ ull f2u(float2 v) {
    ull r; asm("mov.b64 %0,{%1,%2};" : "=l"(r) : "f"(v.x), "f"(v.y)); return r;
}
__device__ __forceinline__ float2 u2f(ull u) {
    float2 v; asm("mov.b64 {%0,%1},%2;" : "=f"(v.x), "=f"(v.y) : "l"(u)); return v;
}
__device__ __forceinline__ ull ffma2(ull a, ull b, ull c) {
    ull d; asm("fma.rn.f32x2 %0,%1,%2,%3;" : "=l"(d) : "l"(a), "l"(b), "l"(c)); return d;
}
__device__ __forceinline__ unsigned int ordered_f32(float f) {
    unsigned int u = __float_as_uint(f);
    return (u & 0x80000000u) ? ~u : (u | 0x80000000u);
}

// logits from qv[10], write to out, contribute to grid argmax. One thread calls.
__device__ __forceinline__ void logits_and_argmax(const float* qv, const float* fc_s,
                                                  float* out, int b) {
    float best = -CUDART_INF_F;
    int   bi   = 0;
    #pragma unroll
    for (int a = 0; a < N_ACT; a++) {
        float s = 0.f;
        #pragma unroll
        for (int o = 0; o < L_Q; o++) s += fc_s[a * L_Q + o] * qv[o];
        out[LOGIT_OFF + b * N_ACT + a] = s;
        if (s > best) { best = s; bi = b * N_ACT + a; }   // strict > keeps first
    }
    const unsigned long long key =
        ((unsigned long long)ordered_f32(best) << 32) |
        (unsigned long long)(0xFFFFFFFFu - (unsigned int)bi);
    atomicMax(&g_best, key);
    __threadfence();
    const unsigned int cnt = atomicAdd(&g_count, 1u);
    if (cnt == B_ - 1u) {                 // exactly B_ contributors grid-wide
        const unsigned long long k2 = atomicMax(&g_best, 0ULL);   // atomic read
        const unsigned int flat = 0xFFFFFFFFu - (unsigned int)(k2 & 0xFFFFFFFFu);
        out[ACT_OFF] = (float)flat;
        g_best = 0ULL;
        __threadfence();
        atomicExch(&g_count, 0u);
    }
}

__global__ __launch_bounds__(NTHR, 2)
void vin_kernel(const float* __restrict__ in,
                const int*   __restrict__ sx_,
                const int*   __restrict__ sy_,
                const int*   __restrict__ kptr,   // may be null
                const float* __restrict__ h_w,
                const float* __restrict__ h_b,
                const float* __restrict__ r_w,
                const float* __restrict__ q_w,
                const float* __restrict__ w,
                const float* __restrict__ fc_w,
                float* __restrict__ out)
{
    __shared__ float  in_s[L_I][INROWS][ISTR];   // 20736 B
    __shared__ __align__(16) float uni[2700];    // h_w staging; later r_s[34*68]
    __shared__ float  rw_s[150];
    __shared__ float  hb_s[150];
    __shared__ float2 qw2[90];                   // q_w replicated for FFMA2
    __shared__ float  fc_s[80];
    __shared__ float  ww_s[90];
    __shared__ float  weffb[20];                 // [0..17]=weff, [18]=beff

    float* r_s = uni;   // [RROWS][RSTR] = 2312 floats, aliases dead h_w staging

    const int tile = blockIdx.x;
    const int b    = blockIdx.y;
    const int gx0  = tile * TILE;
    const int tid  = threadIdx.x;
    const int lane = tid & 31;
    const int wq   = tid >> 5;

    // ============ phase A: stage EVERYTHING coalesced (max MLP, no deps) ============
    {
        const float4* inb4 = (const float4*)(in + (size_t)b * L_I * NPIX);
        #pragma unroll
        for (int i = 0; i < 3; i++) {                       // 1152 float4 total
            const int e = tid + i * NTHR;
            if (e < L_I * INROWS * (IM / 4)) {
                const int ch  = e / (INROWS * (IM / 4));
                const int rem = e - ch * (INROWS * (IM / 4));
                const int row = rem >> 4, c4 = rem & 15;
                const int gr  = gx0 - 2 + row;
                float4 v = make_float4(0.f, 0.f, 0.f, 0.f);
                if (gr >= 0 && gr < IM) v = inb4[ch * (NPIX / 4) + gr * 16 + c4];
                *(float4*)&in_s[ch][row][4 + 4 * c4] = v;
            }
        }
    }
    {   // h_w: 675 float4, fully coalesced
        const float4* hw4 = (const float4*)h_w;
        float4* dst = (float4*)uni;
        #pragma unroll
        for (int e = 0; e < 2; e++) {
            const int i = tid + e * NTHR;
            if (i < 675) dst[i] = hw4[i];
        }
    }
    if (tid < 150) { rw_s[tid] = r_w[tid]; hb_s[tid] = h_b[tid]; }
    if (tid < 90)  { const float v = q_w[tid]; qw2[tid] = make_float2(v, v); ww_s[tid] = w[tid]; }
    if (tid < 80)  fc_s[tid] = fc_w[tid];
    if (tid < 144) {   // in_s column halos (indices 3 and 68)
        const int ch = tid / 72, rr = (tid % 72) >> 1, c = 3 + (tid & 1) * 65;
        in_s[ch][rr][c] = 0.f;
    }
    __syncthreads();   // sync1: staging visible

    // ============ phase B: weight collapse from smem (16 lanes per item) ============
    // weff[j] = sum_c rw[c] * uni[18c + j]  (j=0..17),  beff = sum_c rw[c]*hb[c]
    {
        const int item = tid >> 4;     // 0..31 (items 19..31 dummy)
        const int l    = tid & 15;
        float acc = 0.f;
        if (item < 18) {
            #pragma unroll
            for (int s = 0; s < 10; s++) {
                const int c = l + 16 * s;
                if (c < 150) acc += rw_s[c] * uni[18 * c + item];
            }
        } else if (item == 18) {
            #pragma unroll
            for (int s = 0; s < 10; s++) {
                const int c = l + 16 * s;
                if (c < 150) acc += rw_s[c] * hb_s[c];
            }
        }
        acc += __shfl_xor_sync(0xFFFFFFFFu, acc, 8);
        acc += __shfl_xor_sync(0xFFFFFFFFu, acc, 4);
        acc += __shfl_xor_sync(0xFFFFFFFFu, acc, 2);
        acc += __shfl_xor_sync(0xFFFFFFFFu, acc, 1);
        if (l == 0 && item < 19) weffb[item] = acc;
    }
    const int nz = (tid < 90) ? (ww_s[tid] != 0.f) : 0;
    const int f  = __syncthreads_or(nz);   // sync2: weffb ready, uni free, flag uniform

    // ============ phase C: r = conv3x3(input, weff) + beff into r_s =================
    {   // wr[] scoped here only -> registers die before the conv-q phase
        float wr[18];
        #pragma unroll
        for (int j = 0; j < 18; j++) wr[j] = weffb[j];
        const float be = weffb[18];
        #pragma unroll
        for (int i = 0; i < 5; i++) {                    // 2176 px total
            const int e = tid + i * NTHR;
            if (e < RROWS * IM) {
                const int rx = e >> 6, y = e & 63;
                const int gr = gx0 - 1 + rx;
                float acc = be;
                #pragma unroll
                for (int ci = 0; ci < L_I; ci++)
                    #pragma unroll
                    for (int kh = 0; kh < 3; kh++)
                        #pragma unroll
                        for (int kw = 0; kw < 3; kw++)
                            acc += in_s[ci][rx + kh][y + kw + 3] * wr[ci * 9 + kh * 3 + kw];
                r_s[rx * RSTR + y + 1] = (gr >= 0 && gr < IM) ? acc : 0.f;
            }
        }
    }
    if (tid < 2 * RROWS) {   // r_s column halos (0 and 65)
        const int rr = tid >> 1, c = (tid & 1) * 65;
        r_s[rr * RSTR + c] = 0.f;
    }
    __syncthreads();   // sync3: r_s ready

    float* outb = out + (size_t)b * L_Q * NPIX;

    if (!f) {
        // ============== FAST PATH: w == 0 -> q == conv(r, q_w), FFMA2 ==============
        const int y = 2 * lane;          // pixel pair (y, y+1)
        #pragma unroll
        for (int rs = 0; rs < 2; rs++) {
            const int r0 = wq + rs * 16;  // output row within tile (0..31)
            ull t[9];
            #pragma unroll
            for (int kh = 0; kh < 3; kh++) {
                const float2 lo = *(const float2*)&r_s[(r0 + kh) * RSTR + y];
                const float2 hi = *(const float2*)&r_s[(r0 + kh) * RSTR + y + 2];
                t[kh * 3 + 0] = f2u(lo);
                t[kh * 3 + 1] = pk2(lo.y, hi.x);
                t[kh * 3 + 2] = f2u(hi);
            }
            float* o = outb + (gx0 + r0) * IM + y;
            #pragma unroll
            for (int oc = 0; oc < L_Q; oc++) {
                ull acc = 0ULL;
                #pragma unroll
                for (int j = 0; j < 9; j++)
                    acc = ffma2(t[j], f2u(qw2[oc * 9 + j]), acc);
                *(float2*)(o + oc * NPIX) = u2f(acc);
            }
        }
        // gather + logits + argmax: only the CTA whose rows contain sx
        if (tid == 0) {
            const int sx = sx_[b];
            if (sx >= gx0 && sx < gx0 + TILE) {
                const int sy = sy_[b];
                float qv[L_Q];
                #pragma unroll
                for (int oc = 0; oc < L_Q; oc++) {
                    float a = 0.f;
                    #pragma unroll
                    for (int kh = 0; kh < 3; kh++)
                        #pragma unroll
                        for (int kw = 0; kw < 3; kw++)
                            a += r_s[(sx - gx0 + kh) * RSTR + sy + kw]
                                 * qw2[oc * 9 + kh * 3 + kw].x;
                    qv[oc] = a;
                }
                logits_and_argmax(qv, fc_s, out, b);
            }
        }
        return;
    }

    // ================== SLOW PATH: w != 0, full k-iteration (tile 0 only) ==========
    if (tile != 0) return;
    {
        const int kk = (kptr != nullptr) ? *kptr : 40;
        const float* inb = in + (size_t)b * L_I * NPIX;

        for (int i = tid; i < IMP * IMP; i += NTHR) {
            g_r[b][i] = 0.f; g_vb[0][b][i] = 0.f; g_vb[1][b][i] = 0.f;
        }
        __syncthreads();

        // full-image r (weights from smem; cold path, perf irrelevant)
        for (int e = tid; e < NPIX; e += NTHR) {
            const int x = e >> 6, y = e & 63;
            float acc = weffb[18];
            for (int ci = 0; ci < L_I; ci++)
                for (int kh = 0; kh < 3; kh++) {
                    const int ix = x + kh - 1;
                    if (ix < 0 || ix >= IM) continue;
                    for (int kw = 0; kw < 3; kw++) {
                        const int iy = y + kw - 1;
                        if (iy < 0 || iy >= IM) continue;
                        acc += inb[ci * NPIX + ix * IM + iy] * weffb[ci * 9 + kh * 3 + kw];
                    }
                }
            g_r[b][(x + 1) * IMP + y + 1] = acc;
        }
        __syncthreads();

        // qr + v0
        for (int e = tid; e < NPIX; e += NTHR) {
            const int x = e >> 6, y = e & 63;
            float t[9];
            for (int kh = 0; kh < 3; kh++)
                for (int kw = 0; kw < 3; kw++)
                    t[kh * 3 + kw] = g_r[b][(x + kh) * IMP + y + kw];
            float vmax = -CUDART_INF_F;
            for (int oc = 0; oc < L_Q; oc++) {
                float a = 0.f;
                for (int j = 0; j < 9; j++) a += t[j] * qw2[oc * 9 + j].x;
                g_qr[b][oc][e] = a;
                vmax = fmaxf(vmax, a);
            }
            g_vb[0][b][(x + 1) * IMP + y + 1] = vmax;
        }
        __syncthreads();

        int cur = 0;
        for (int it = 0; it < kk - 1; it++) {
            for (int e = tid; e < NPIX; e += NTHR) {
                const int x = e >> 6, y = e & 63;
                float t[9];
                for (int kh = 0; kh < 3; kh++)
                    for (int kw = 0; kw < 3; kw++)
                        t[kh * 3 + kw] = g_vb[cur][b][(x + kh) * IMP + y + kw];
                float vmax = -CUDART_INF_F;
                for (int oc = 0; oc < L_Q; oc++) {
                    float a = g_qr[b][oc][e];
                    for (int j = 0; j < 9; j++) a += t[j] * ww_s[oc * 9 + j];
                    vmax = fmaxf(vmax, a);
                }
                g_vb[cur ^ 1][b][(x + 1) * IMP + y + 1] = vmax;
            }
            cur ^= 1;
            __syncthreads();
        }

        // final q = qr + conv(v, w)
        for (int e = tid; e < NPIX; e += NTHR) {
            const int x = e >> 6, y = e & 63;
            float t[9];
            for (int kh = 0; kh < 3; kh++)
                for (int kw = 0; kw < 3; kw++)
                    t[kh * 3 + kw] = g_vb[cur][b][(x + kh) * IMP + y + kw];
            for (int oc = 0; oc < L_Q; oc++) {
                float a = g_qr[b][oc][e];
                for (int j = 0; j < 9; j++) a += t[j] * ww_s[oc * 9 + j];
                outb[oc * NPIX + e] = a;
            }
        }
        __syncthreads();

        if (tid == 0) {
            const int sx = sx_[b], sy = sy_[b];
            float qv[L_Q];
            for (int oc = 0; oc < L_Q; oc++) {
                float a = g_qr[b][oc][sx * IM + sy];
                for (int kh = 0; kh < 3; kh++)
                    for (int kw = 0; kw < 3; kw++)
                        a += g_vb[cur][b][(sx + kh) * IMP + sy + kw]
                             * ww_s[oc * 9 + kh * 3 + kw];
                qv[oc] = a;
            }
            logits_and_argmax(qv, fc_s, out, b);
        }
    }
}

extern "C" void kernel_launch(void* const* d_in, const int* in_sizes, int n_in,
                              void* d_out, int out_size)
{
    // Inputs: input_view, state_x, state_y, [k], h_w, h_b, r_w, q_w, w, fc_w
    int hw_idx = -1;
    for (int i = 0; i < n_in; i++) {
        if (in_sizes[i] == 2700) { hw_idx = i; break; }
    }
    if (hw_idx < 0) hw_idx = 4;

    const float* in_v = (const float*)d_in[0];
    const int*   sx   = (const int*)d_in[1];
    const int*   sy   = (const int*)d_in[2];
    const int*   kptr = (hw_idx == 4) ? (const int*)d_in[3] : nullptr;
    const float* h_w  = (const float*)d_in[hw_idx];
    const float* h_b  = (const float*)d_in[hw_idx + 1];
    const float* r_w  = (const float*)d_in[hw_idx + 2];
    const float* q_w  = (const float*)d_in[hw_idx + 3];
    const float* w    = (const float*)d_in[hw_idx + 4];
    const float* fc_w = (const float*)d_in[hw_idx + 5];
    float* out = (float*)d_out;

    dim3 grid(TILES, B_);
    vin_kernel<<<grid, NTHR>>>(in_v, sx, sy, kptr, h_w, h_b, r_w,
                               q_w, w, fc_w, out);
}

// round 9
// speedup vs baseline: 4.0702x; 4.0702x over previous
#include <cuda_runtime.h>
#include <math_constants.h>

// Problem constants (fixed by the dataset)
#define B_      128
#define L_I     2
#define L_Q     10
#define N_ACT   8
#define IM      64
#define IMP     66
#define NPIX    4096
#define NTHR    1024
#define PPT     4            // pixels per thread = 4096/1024

// smem layout (bytes) — dynamic, R2-proven
#define OFF_QR    0          // qr 10*4096*4=163840 (aliased: input 32768 + wt staging)
#define OFF_R     163840     // 66*66*4 = 17424
#define OFF_V     181264     // 66*66*4 = 17424
#define OFF_QW    198688     // 90*4
#define OFF_WW    199048     // 90*4
#define OFF_FC    199408     // 80*4
#define OFF_QOUT  199728     // 10*4
#define OFF_LARR  199768     // 8*4
#define SMEM_TOT  199800

// staging float-indices inside the qr alias region (after the 8192-float input)
#define STG_HW    8192       // 2700
#define STG_RW    10892      // 150
#define STG_HB    11042      // 150

#define Q_ELEMS   (B_ * L_Q * NPIX)       // 5242880
#define LOGIT_OFF Q_ELEMS
#define ACT_OFF   (Q_ELEMS + B_ * N_ACT)  // 5243904

// grid-wide argmax state (self-resetting each launch -> graph-replay safe)
__device__ unsigned long long g_best  = 0ULL;
__device__ unsigned int       g_count = 0u;

__device__ __forceinline__ unsigned int ordered_f32(float f) {
    unsigned int u = __float_as_uint(f);
    return (u & 0x80000000u) ? ~u : (u | 0x80000000u);
}

__global__ __launch_bounds__(NTHR, 1)
void vin_main_kernel(const float* __restrict__ in,
                     const int*   __restrict__ sx_,
                     const int*   __restrict__ sy_,
                     const int*   __restrict__ kptr,   // may be null
                     const float* __restrict__ h_w,
                     const float* __restrict__ h_b,
                     const float* __restrict__ r_w,
                     const float* __restrict__ q_w,
                     const float* __restrict__ w,
                     const float* __restrict__ fc_w,
                     float* __restrict__ out)
{
    extern __shared__ __align__(16) char smem[];
    float* qr    = (float*)(smem + OFF_QR);    // [10*4096] slow path only
    float* in_s  = (float*)(smem + OFF_QR);    // alias [2*4096]
    float* wt_s  = (float*)(smem + OFF_QR);    // alias, STG_* float indices
    float* r_s   = (float*)(smem + OFF_R);     // [66*66] zero halo
    float* v_s   = (float*)(smem + OFF_V);     // [66*66] zero halo (slow path)
    float* qw_s  = (float*)(smem + OFF_QW);    // [90]
    float* ww_s  = (float*)(smem + OFF_WW);    // [90]
    float* fc_s  = (float*)(smem + OFF_FC);    // [80]
    float* qout  = (float*)(smem + OFF_QOUT);  // [10]
    float* larr  = (float*)(smem + OFF_LARR);  // [8]
    __shared__ float weffb[20];                // [0..17]=weff, [18]=beff

    const int b   = blockIdx.x;
    const int tid = threadIdx.x;

    // ================ S0: stage everything (coalesced), zero r_s/v_s ================
    {
        const float4* src = (const float4*)(in + (size_t)b * L_I * NPIX);
        float4* dst = (float4*)in_s;
        #pragma unroll
        for (int i = 0; i < (L_I * NPIX / 4) / NTHR; i++)       // 2 rounds
            dst[tid + i * NTHR] = src[tid + i * NTHR];
    }
    {   // h_w: 675 float4, coalesced
        const float4* hw4 = (const float4*)h_w;
        float4* dst = (float4*)(wt_s + STG_HW);
        if (tid < 675) dst[tid] = hw4[tid];
    }
    if (tid < 150) { wt_s[STG_RW + tid] = r_w[tid]; wt_s[STG_HB + tid] = h_b[tid]; }
    if (tid < 90)  { qw_s[tid] = q_w[tid]; ww_s[tid] = w[tid]; }
    if (tid < 80)  fc_s[tid] = fc_w[tid];
    #pragma unroll
    for (int i = 0; i < 5; i++) {            // zero 66x66 r_s and v_s
        const int e = tid + i * NTHR;
        if (e < IMP * IMP) { r_s[e] = 0.f; v_s[e] = 0.f; }
    }
    __syncthreads();   // sync1

    // ================ S1: weight collapse from smem (16 lanes per item) =============
    // weff[i*9+t] = sum_c r_w[c] * h_w[(c*2+i)*9+t];  beff = sum_c r_w[c]*h_b[c]
    {
        const int item = tid >> 4;        // 0..63 (only 0..18 meaningful)
        const int l    = tid & 15;
        float acc = 0.f;
        if (item < 18) {
            const int i = item / 9, t = item % 9;
            #pragma unroll
            for (int s = 0; s < 10; s++) {
                const int c = l + 16 * s;
                if (c < 150)
                    acc += wt_s[STG_RW + c] * wt_s[STG_HW + (c * L_I + i) * 9 + t];
            }
        } else if (item == 18) {
            #pragma unroll
            for (int s = 0; s < 10; s++) {
                const int c = l + 16 * s;
                if (c < 150) acc += wt_s[STG_RW + c] * wt_s[STG_HB + c];
            }
        }
        acc += __shfl_xor_sync(0xFFFFFFFFu, acc, 8);
        acc += __shfl_xor_sync(0xFFFFFFFFu, acc, 4);
        acc += __shfl_xor_sync(0xFFFFFFFFu, acc, 2);
        acc += __shfl_xor_sync(0xFFFFFFFFu, acc, 1);
        if (l == 0 && item < 19) weffb[item] = acc;
    }
    const int nz = (tid < 90) ? (ww_s[tid] != 0.f) : 0;
    const int f  = __syncthreads_or(nz);   // sync2: weffb ready, flag uniform

    // ================ S2: r = conv3x3(input, weff, pad=1) + beff ====================
    {
        float wr[18];
        #pragma unroll
        for (int j = 0; j < 18; j++) wr[j] = weffb[j];
        const float be = weffb[18];
        #pragma unroll
        for (int c = 0; c < PPT; c++) {
            const int p = tid + c * NTHR;
            const int x = p >> 6, y = p & 63;
            float acc = be;
            #pragma unroll
            for (int i = 0; i < L_I; i++) {
                #pragma unroll
                for (int kh = 0; kh < 3; kh++) {
                    const int ix = x + kh - 1;
                    if (ix < 0 || ix > 63) continue;
                    #pragma unroll
                    for (int kw = 0; kw < 3; kw++) {
                        const int iy = y + kw - 1;
                        if (iy < 0 || iy > 63) continue;
                        acc += in_s[(i * IM + ix) * IM + iy] * wr[i * 9 + kh * 3 + kw];
                    }
                }
            }
            r_s[(x + 1) * IMP + (y + 1)] = acc;
        }
    }
    __syncthreads();   // sync3: r_s ready; in_s/wt_s (qr region) free

    float* outb = out + (size_t)b * L_Q * NPIX;

    if (!f) {
        // ============ FAST PATH: w == 0 -> q == conv(r, q_w), scalar FFMA ===========
        // each thread: 4 consecutive pixels (one quad) across all 10 channels
        const int row = tid >> 4;            // 0..63
        const int y0  = (tid & 15) * 4;      // 0,4,...,60
        // window: r_s rows row..row+2, raw cols y0..y0+5 (pixel (row,y) taps raw y..y+2)
        float wnd[3][6];
        #pragma unroll
        for (int kh = 0; kh < 3; kh++) {
            #pragma unroll
            for (int m = 0; m < 3; m++) {
                const float2 v = *(const float2*)&r_s[(row + kh) * IMP + y0 + 2 * m];
                wnd[kh][2 * m]     = v.x;
                wnd[kh][2 * m + 1] = v.y;
            }
        }
        float* obase = outb + row * IM + y0;
        #pragma unroll
        for (int chk = 0; chk < 5; chk++) {      // 2 output channels per chunk
            float qa[18];
            #pragma unroll
            for (int j = 0; j < 18; j++) qa[j] = qw_s[chk * 18 + j];
            float a0[4], a1[4];
            #pragma unroll
            for (int px = 0; px < 4; px++) {
                float s0 = 0.f, s1 = 0.f;
                #pragma unroll
                for (int kh = 0; kh < 3; kh++)
                    #pragma unroll
                    for (int kw = 0; kw < 3; kw++) {
                        const float t = wnd[kh][px + kw];
                        s0 += t * qa[kh * 3 + kw];
                        s1 += t * qa[9 + kh * 3 + kw];
                    }
                a0[px] = s0; a1[px] = s1;
            }
            *(float4*)(obase + (2 * chk)     * NPIX) = make_float4(a0[0], a0[1], a0[2], a0[3]);
            *(float4*)(obase + (2 * chk + 1) * NPIX) = make_float4(a1[0], a1[1], a1[2], a1[3]);
        }
        // gather q[b,:,sx,sy] from r_s (recompute, 10x9 FMA)
        {
            const int sx = sx_[b], sy = sy_[b];
            if (tid < L_Q) {
                float a = 0.f;
                #pragma unroll
                for (int kh = 0; kh < 3; kh++)
                    #pragma unroll
                    for (int kw = 0; kw < 3; kw++)
                        a += r_s[(sx + kh) * IMP + sy + kw] * qw_s[tid * 9 + kh * 3 + kw];
                qout[tid] = a;
            }
        }
        __syncthreads();
    } else {
        // ============ SLOW PATH: generic k-iteration loop (w != 0) ==================
        // qr[o] = conv(r, q_w[o]); v0 = max_o qr[o]
        #pragma unroll
        for (int c = 0; c < PPT; c++) {
            const int p = tid + c * NTHR;
            const int x = p >> 6, y = p & 63;
            float t[9];
            #pragma unroll
            for (int kh = 0; kh < 3; kh++)
                #pragma unroll
                for (int kw = 0; kw < 3; kw++)
                    t[kh * 3 + kw] = r_s[(x + kh) * IMP + (y + kw)];
            float vmax = -CUDART_INF_F;
            #pragma unroll
            for (int o = 0; o < L_Q; o++) {
                float a = 0.f;
                #pragma unroll
                for (int j = 0; j < 9; j++) a += t[j] * qw_s[o * 9 + j];
                qr[o * NPIX + p] = a;
                vmax = fmaxf(vmax, a);
            }
            v_s[(x + 1) * IMP + (y + 1)] = vmax;
        }
        __syncthreads();

        const int kk = (kptr != nullptr) ? *kptr : 40;
        for (int it = 0; it < kk - 1; it++) {
            float nv[PPT];
            #pragma unroll
            for (int c = 0; c < PPT; c++) {
                const int p = tid + c * NTHR;
                const int x = p >> 6, y = p & 63;
                float t[9];
                #pragma unroll
                for (int kh = 0; kh < 3; kh++)
                    #pragma unroll
                    for (int kw = 0; kw < 3; kw++)
                        t[kh * 3 + kw] = v_s[(x + kh) * IMP + (y + kw)];
                float vmax = -CUDART_INF_F;
                #pragma unroll
                for (int o = 0; o < L_Q; o++) {
                    float a = qr[o * NPIX + p];
                    #pragma unroll
                    for (int j = 0; j < 9; j++) a += t[j] * ww_s[o * 9 + j];
                    vmax = fmaxf(vmax, a);
                }
                nv[c] = vmax;
            }
            __syncthreads();
            #pragma unroll
            for (int c = 0; c < PPT; c++) {
                const int p = tid + c * NTHR;
                const int x = p >> 6, y = p & 63;
                v_s[(x + 1) * IMP + (y + 1)] = nv[c];
            }
            __syncthreads();
        }

        // final q = qr + conv(v, w) -> gmem
        #pragma unroll
        for (int c = 0; c < PPT; c++) {
            const int p = tid + c * NTHR;
            const int x = p >> 6, y = p & 63;
            float t[9];
            #pragma unroll
            for (int kh = 0; kh < 3; kh++)
                #pragma unroll
                for (int kw = 0; kw < 3; kw++)
                    t[kh * 3 + kw] = v_s[(x + kh) * IMP + (y + kw)];
            #pragma unroll
            for (int o = 0; o < L_Q; o++) {
                float a = qr[o * NPIX + p];
                #pragma unroll
                for (int j = 0; j < 9; j++) a += t[j] * ww_s[o * 9 + j];
                outb[o * NPIX + p] = a;
            }
        }
        // gather q[b,:,sx,sy]
        const int sx = sx_[b], sy = sy_[b];
        if (tid < L_Q) {
            float a = qr[tid * NPIX + sx * IM + sy];
            #pragma unroll
            for (int kh = 0; kh < 3; kh++)
                #pragma unroll
                for (int kw = 0; kw < 3; kw++)
                    a += v_s[(sx + kh) * IMP + sy + kw] * ww_s[tid * 9 + kh * 3 + kw];
            qout[tid] = a;
        }
        __syncthreads();
    }

    // ================ epilogue: logits + fused grid-wide argmax =====================
    if (tid < N_ACT) {
        float a = 0.f;
        #pragma unroll
        for (int o = 0; o < L_Q; o++) a += fc_s[tid * L_Q + o] * qout[o];
        out[LOGIT_OFF + b * N_ACT + tid] = a;
        larr[tid] = a;
    }
    __syncthreads();
    if (tid == 0) {
        float best = larr[0];
        int   bi   = b * N_ACT;
        #pragma unroll
        for (int a = 1; a < N_ACT; a++) {
            if (larr[a] > best) { best = larr[a]; bi = b * N_ACT + a; }
        }
        const unsigned long long key =
            ((unsigned long long)ordered_f32(best) << 32) |
            (unsigned long long)(0xFFFFFFFFu - (unsigned int)bi);
        atomicMax(&g_best, key);
        __threadfence();
        const unsigned int cnt = atomicAdd(&g_count, 1u);
        if (cnt == B_ - 1u) {
            const unsigned long long k2 = atomicMax(&g_best, 0ULL); // atomic read
            const unsigned int flat = 0xFFFFFFFFu - (unsigned int)(k2 & 0xFFFFFFFFu);
            out[ACT_OFF] = (float)flat;
            g_best = 0ULL;
            __threadfence();
            atomicExch(&g_count, 0u);
        }
    }
}

extern "C" void kernel_launch(void* const* d_in, const int* in_sizes, int n_in,
                              void* d_out, int out_size)
{
    // Inputs: input_view, state_x, state_y, [k], h_w, h_b, r_w, q_w, w, fc_w
    int hw_idx = -1;
    for (int i = 0; i < n_in; i++) {
        if (in_sizes[i] == 2700) { hw_idx = i; break; }
    }
    if (hw_idx < 0) hw_idx = 4;

    const float* in_v = (const float*)d_in[0];
    const int*   sx   = (const int*)d_in[1];
    const int*   sy   = (const int*)d_in[2];
    const int*   kptr = (hw_idx == 4) ? (const int*)d_in[3] : nullptr;
    const float* h_w  = (const float*)d_in[hw_idx];
    const float* h_b  = (const float*)d_in[hw_idx + 1];
    const float* r_w  = (const float*)d_in[hw_idx + 2];
    const float* q_w  = (const float*)d_in[hw_idx + 3];
    const float* w    = (const float*)d_in[hw_idx + 4];
    const float* fc_w = (const float*)d_in[hw_idx + 5];
    float* out = (float*)d_out;

    cudaFuncSetAttribute(vin_main_kernel,
                         cudaFuncAttributeMaxDynamicSharedMemorySize, SMEM_TOT);

    vin_main_kernel<<<B_, NTHR, SMEM_TOT>>>(in_v, sx, sy, kptr, h_w, h_b, r_w,
                                            q_w, w, fc_w, out);
}